// round 11
// baseline (speedup 1.0000x reference)
#include <cuda_runtime.h>

#define SLEN 1024
#define BATCH 48
#define NTHREADS 128
#define QPT 4
#define QBLK (NTHREADS * QPT)   // 512 queries per block
#define NROWS (BATCH * SLEN)    // 49152
#define NPART 96                // 48 batches * 2 halves
#define NT4   (SLEN / 4)        // 256 key-quads

// Scratch (allocation-free rule: __device__ globals)
// SoA: g_out[ch][row] for fully coalesced stores (attn) and loads (bnfc).
__device__ float g_out[9][NROWS];
__device__ float g_ps[9 * NPART];       // partial sums  per channel
__device__ float g_pq[9 * NPART];       // partial sumsq per channel
__device__ float g_fw[27];              // BN-folded FC weights
__device__ float g_fb[3];               // BN-folded FC bias

typedef unsigned long long ull;

__device__ __forceinline__ float ex2f(float x) {
    float y; asm("ex2.approx.ftz.f32 %0, %1;" : "=f"(y) : "f"(x)); return y;
}
__device__ __forceinline__ float rcpf(float x) {
    float y; asm("rcp.approx.ftz.f32 %0, %1;" : "=f"(y) : "f"(x)); return y;
}
// ---- f32x2 packed math (sm_100+) ----
__device__ __forceinline__ ull pk2(float lo, float hi) {
    ull d; asm("mov.b64 %0, {%1, %2};" : "=l"(d) : "f"(lo), "f"(hi)); return d;
}
__device__ __forceinline__ void upk2(ull d, float& lo, float& hi) {
    asm("mov.b64 {%0, %1}, %2;" : "=f"(lo), "=f"(hi) : "l"(d));
}
__device__ __forceinline__ ull fma2(ull a, ull b, ull c) {
    ull d; asm("fma.rn.f32x2 %0, %1, %2, %3;" : "=l"(d) : "l"(a), "l"(b), "l"(c)); return d;
}
__device__ __forceinline__ ull mul2(ull a, ull b) {
    ull d; asm("mul.rn.f32x2 %0, %1, %2;" : "=l"(d) : "l"(a), "l"(b)); return d;
}
__device__ __forceinline__ ull add2(ull a, ull b) {
    ull d; asm("add.rn.f32x2 %0, %1, %2;" : "=l"(d) : "l"(a), "l"(b)); return d;
}

struct Tile { ulonglong2 kx, ky, kz, vx, vy, vz; };

struct SmemView {
    const ulonglong2 *kx, *ky, *kz, *vx, *vy, *vz;
};

__device__ __forceinline__ void load_tile(Tile& T, const SmemView& sv, int idx) {
    T.kx = sv.kx[idx]; T.ky = sv.ky[idx]; T.kz = sv.kz[idx];
    T.vx = sv.vx[idx]; T.vy = sv.vy[idx]; T.vz = sv.vz[idx];
}

__device__ __forceinline__ void body(const Tile& T,
    const ull (&qx2)[QPT], const ull (&qy2)[QPT], const ull (&qz2)[QPT],
    ull (&ssum2)[QPT], ull (&accx2)[QPT], ull (&accy2)[QPT], ull (&accz2)[QPT])
{
    #pragma unroll
    for (int p = 0; p < 2; p++) {
        ull kxx = p ? T.kx.y : T.kx.x;
        ull kyy = p ? T.ky.y : T.ky.x;
        ull kzz = p ? T.kz.y : T.kz.x;
        ull vxx = p ? T.vx.y : T.vx.x;
        ull vyy = p ? T.vy.y : T.vy.x;
        ull vzz = p ? T.vz.y : T.vz.x;
        #pragma unroll
        for (int i = 0; i < QPT; i++) {
            ull sc2 = fma2(qz2[i], kzz, fma2(qy2[i], kyy, mul2(qx2[i], kxx)));
            float s0, s1; upk2(sc2, s0, s1);
            ull w2 = pk2(ex2f(s0), ex2f(s1));
            ssum2[i] = add2(ssum2[i], w2);
            accx2[i] = fma2(w2, vxx, accx2[i]);
            accy2[i] = fma2(w2, vyy, accy2[i]);
            accz2[i] = fma2(w2, vzz, accz2[i]);
        }
    }
}

// Grid: (half=2, combo=3, batch=48). Block: 128 threads, 4 queries each.
// K/V stored component-major in smem so LDS.128 yields 4 consecutive keys'
// worth of one component = two pre-packed f32x2 key-pairs (no pack MOVs).
__global__ __launch_bounds__(NTHREADS) void attn_kernel(
    const float* __restrict__ x,
    const float* __restrict__ WQ, const float* __restrict__ bQ,
    const float* __restrict__ WK, const float* __restrict__ bK,
    const float* __restrict__ WV, const float* __restrict__ bV)
{
    __shared__ __align__(16) float sKx[SLEN], sKy[SLEN], sKz[SLEN];
    __shared__ __align__(16) float sVx[SLEN], sVy[SLEN], sVz[SLEN];
    __shared__ float red[6][NTHREADS];

    const int half = blockIdx.x;
    const int c    = blockIdx.y;
    const int b    = blockIdx.z;
    // a1=attn(Q2,K0,V1) ch0-2 ; a2=attn(Q0,K1,V2) ch3-5 ; a3=attn(Q1,K2,V0) ch6-8
    const int qb = (c + 2) % 3;
    const int kb = c;
    const int vb = (c + 1) % 3;
    const int tid = threadIdx.x;

    // band/batch base pointers into x: layout (3, B, S, 3)
    const float* xk = x + ((size_t)kb * BATCH + b) * SLEN * 3;
    const float* xv = x + ((size_t)vb * BATCH + b) * SLEN * 3;
    const float* xq = x + ((size_t)qb * BATCH + b) * SLEN * 3;

    // projection weights (tiny, L1/L2 resident)
    float wk[9], bkv[3], wv[9], bvv[3];
    #pragma unroll
    for (int i = 0; i < 9; i++) { wk[i] = WK[kb * 9 + i]; wv[i] = WV[vb * 9 + i]; }
    #pragma unroll
    for (int i = 0; i < 3; i++) { bkv[i] = bK[kb * 3 + i]; bvv[i] = bV[vb * 3 + i]; }

    // Fill K, V tiles (component-major)
    for (int s = tid; s < SLEN; s += NTHREADS) {
        float x0 = xk[s * 3 + 0], x1 = xk[s * 3 + 1], x2 = xk[s * 3 + 2];
        sKx[s] = fmaf(wk[2], x2, fmaf(wk[1], x1, fmaf(wk[0], x0, bkv[0])));
        sKy[s] = fmaf(wk[5], x2, fmaf(wk[4], x1, fmaf(wk[3], x0, bkv[1])));
        sKz[s] = fmaf(wk[8], x2, fmaf(wk[7], x1, fmaf(wk[6], x0, bkv[2])));
        float y0 = xv[s * 3 + 0], y1 = xv[s * 3 + 1], y2 = xv[s * 3 + 2];
        sVx[s] = fmaf(wv[2], y2, fmaf(wv[1], y1, fmaf(wv[0], y0, bvv[0])));
        sVy[s] = fmaf(wv[5], y2, fmaf(wv[4], y1, fmaf(wv[3], y0, bvv[1])));
        sVz[s] = fmaf(wv[8], y2, fmaf(wv[7], y1, fmaf(wv[6], y0, bvv[2])));
    }
    __syncthreads();

    // Per-thread queries, pre-scaled by log2(e)/sqrt(3) so ex2(q.k) == exp(score),
    // duplicated into both f32x2 lanes (key-pair broadcast).
    const float QS = (float)(1.4426950408889634 / 1.7320508075688772);
    float wq[9], bqv[3];
    #pragma unroll
    for (int i = 0; i < 9; i++) wq[i] = WQ[qb * 9 + i];
    #pragma unroll
    for (int i = 0; i < 3; i++) bqv[i] = bQ[qb * 3 + i];

    const int q0 = half * QBLK;
    ull qx2[QPT], qy2[QPT], qz2[QPT];
    ull ssum2[QPT], accx2[QPT], accy2[QPT], accz2[QPT];
    #pragma unroll
    for (int i = 0; i < QPT; i++) {
        int s = q0 + tid + i * NTHREADS;
        float x0 = xq[s * 3 + 0], x1 = xq[s * 3 + 1], x2 = xq[s * 3 + 2];
        float a0 = QS * fmaf(wq[2], x2, fmaf(wq[1], x1, fmaf(wq[0], x0, bqv[0])));
        float a1 = QS * fmaf(wq[5], x2, fmaf(wq[4], x1, fmaf(wq[3], x0, bqv[1])));
        float a2 = QS * fmaf(wq[8], x2, fmaf(wq[7], x1, fmaf(wq[6], x0, bqv[2])));
        qx2[i] = pk2(a0, a0); qy2[i] = pk2(a1, a1); qz2[i] = pk2(a2, a2);
        ssum2[i] = 0ull; accx2[i] = 0ull; accy2[i] = 0ull; accz2[i] = 0ull;
    }

    SmemView sv = { (const ulonglong2*)sKx, (const ulonglong2*)sKy,
                    (const ulonglong2*)sKz, (const ulonglong2*)sVx,
                    (const ulonglong2*)sVy, (const ulonglong2*)sVz };

    // Ping-pong software pipeline: tile t+1 fetched (LDS.128 broadcast,
    // ~29 cyc latency) before the ~64-cyc MUFU body of tile t.
    // No tile-copy MOVs, no per-iter branch; final prefetch index clamped.
    Tile A, B;
    load_tile(A, sv, 0);
    for (int t4 = 0; t4 < NT4; t4 += 2) {
        load_tile(B, sv, t4 + 1);
        body(A, qx2, qy2, qz2, ssum2, accx2, accy2, accz2);
        load_tile(A, sv, min(t4 + 2, NT4 - 1));
        body(B, qx2, qy2, qz2, ssum2, accx2, accy2, accz2);
    }

    // Finalize (horizontal add of the two key-parity lanes), write out
    // (SoA, coalesced), accumulate per-channel partial stats.
    float ps[3] = {0.f, 0.f, 0.f}, pq[3] = {0.f, 0.f, 0.f};
    #pragma unroll
    for (int i = 0; i < QPT; i++) {
        float slo, shi, xlo, xhi, ylo, yhi, zlo, zhi;
        upk2(ssum2[i], slo, shi);
        upk2(accx2[i], xlo, xhi);
        upk2(accy2[i], ylo, yhi);
        upk2(accz2[i], zlo, zhi);
        float inv = rcpf(slo + shi);
        float o0 = (xlo + xhi) * inv, o1 = (ylo + yhi) * inv, o2 = (zlo + zhi) * inv;
        int row = b * SLEN + q0 + tid + i * NTHREADS;
        g_out[3 * c + 0][row] = o0;
        g_out[3 * c + 1][row] = o1;
        g_out[3 * c + 2][row] = o2;
        ps[0] += o0; ps[1] += o1; ps[2] += o2;
        pq[0] += o0 * o0; pq[1] += o1 * o1; pq[2] += o2 * o2;
    }

    // Deterministic block reduction of partial stats
    red[0][tid] = ps[0]; red[1][tid] = ps[1]; red[2][tid] = ps[2];
    red[3][tid] = pq[0]; red[4][tid] = pq[1]; red[5][tid] = pq[2];
    __syncthreads();
    for (int st = NTHREADS / 2; st > 0; st >>= 1) {
        if (tid < st) {
            #pragma unroll
            for (int j = 0; j < 6; j++) red[j][tid] += red[j][tid + st];
        }
        __syncthreads();
    }
    if (tid == 0) {
        int col = b * 2 + half;
        #pragma unroll
        for (int e = 0; e < 3; e++) {
            g_ps[(3 * c + e) * NPART + col] = red[e][0];
            g_pq[(3 * c + e) * NPART + col] = red[3 + e][0];
        }
    }
}

// Single-block: reduce stats partials once, fold BN into FC, publish w2/b2.
__global__ __launch_bounds__(NPART) void fold_kernel(
    const float* __restrict__ gamma, const float* __restrict__ beta,
    const float* __restrict__ fcw, const float* __restrict__ fcb)
{
    __shared__ float sps[9][NPART], spq[9][NPART];
    __shared__ float scale[9], shift[9];
    const int tid = threadIdx.x;

    // Stage partials: 96 threads x 9 channels, coalesced per channel.
    #pragma unroll
    for (int ch = 0; ch < 9; ch++) {
        sps[ch][tid] = g_ps[ch * NPART + tid];
        spq[ch][tid] = g_pq[ch * NPART + tid];
    }
    __syncthreads();
    // Tree-reduce 96 -> 3 per channel (fixed order, deterministic).
    for (int st = NPART / 2; st >= 3; st >>= 1) {
        for (int idx = tid; idx < 9 * st; idx += NPART) {
            int ch = idx / st, j = idx % st;
            sps[ch][j] += sps[ch][j + st];
            spq[ch][j] += spq[ch][j + st];
        }
        __syncthreads();
    }
    if (tid < 9) {
        float s  = sps[tid][0] + sps[tid][1] + sps[tid][2];
        float qq = spq[tid][0] + spq[tid][1] + spq[tid][2];
        float invn = 1.0f / (float)NROWS;
        float mean = s * invn;
        float var  = qq * invn - mean * mean;
        float sc = gamma[tid] * rsqrtf(var + 1e-5f);
        scale[tid] = sc;
        shift[tid] = beta[tid] - mean * sc;
    }
    __syncthreads();
    if (tid < 27) g_fw[tid] = fcw[tid] * scale[tid % 9];
    if (tid < 3) {
        float a = fcb[tid];
        #pragma unroll
        for (int cc = 0; cc < 9; cc++) a = fmaf(fcw[tid * 9 + cc], shift[cc], a);
        g_fb[tid] = a;
    }
}

// GEMV epilogue: y = g_out @ w2^T + b2 (BN already folded by fold_kernel).
__global__ __launch_bounds__(256) void bnfc_kernel(float* __restrict__ out)
{
    __shared__ float w2[27], b2s[3];
    const int tid = threadIdx.x;

    if (tid < 27) w2[tid] = g_fw[tid];
    if (tid < 3)  b2s[tid] = g_fb[tid];
    __syncthreads();

    int row = blockIdx.x * blockDim.x + tid;
    float v[9];
    #pragma unroll
    for (int cc = 0; cc < 9; cc++) v[cc] = g_out[cc][row];   // coalesced (SoA)
    #pragma unroll
    for (int j = 0; j < 3; j++) {
        float y = b2s[j];
        #pragma unroll
        for (int cc = 0; cc < 9; cc++) y = fmaf(w2[j * 9 + cc], v[cc], y);
        out[row * 3 + j] = y;
    }
}

extern "C" void kernel_launch(void* const* d_in, const int* in_sizes, int n_in,
                              void* d_out, int out_size)
{
    const float* x     = (const float*)d_in[0];
    const float* WQ    = (const float*)d_in[1];
    const float* bQ    = (const float*)d_in[2];
    const float* WK    = (const float*)d_in[3];
    const float* bK    = (const float*)d_in[4];
    const float* WV    = (const float*)d_in[5];
    const float* bV    = (const float*)d_in[6];
    const float* gamma = (const float*)d_in[7];
    const float* beta  = (const float*)d_in[8];
    const float* fcw   = (const float*)d_in[9];
    const float* fcb   = (const float*)d_in[10];

    dim3 g1(2, 3, BATCH);
    attn_kernel<<<g1, NTHREADS>>>(x, WQ, bQ, WK, bK, WV, bV);
    fold_kernel<<<1, NPART>>>(gamma, beta, fcw, fcb);
    bnfc_kernel<<<NROWS / 256, 256>>>((float*)d_out);
}

// round 13
// speedup vs baseline: 1.0906x; 1.0906x over previous
#include <cuda_runtime.h>

#define SLEN 1024
#define BATCH 48
#define NTHREADS 256
#define QPT 2
#define QBLK (NTHREADS * QPT)   // 512 queries per block
#define NROWS (BATCH * SLEN)    // 49152
#define NPART 96                // 48 batches * 2 halves
#define NT4   (SLEN / 4)        // 256 key-quads

// Scratch (allocation-free rule: __device__ globals)
// SoA: g_out[ch][row] for fully coalesced stores (attn) and loads (bnfc).
__device__ float g_out[9][NROWS];
__device__ float g_ps[9 * NPART];       // partial sums  per channel
__device__ float g_pq[9 * NPART];       // partial sumsq per channel
__device__ float g_fw[27];              // BN-folded FC weights
__device__ float g_fb[3];               // BN-folded FC bias

typedef unsigned long long ull;

__device__ __forceinline__ float ex2f(float x) {
    float y; asm("ex2.approx.ftz.f32 %0, %1;" : "=f"(y) : "f"(x)); return y;
}
__device__ __forceinline__ float rcpf(float x) {
    float y; asm("rcp.approx.ftz.f32 %0, %1;" : "=f"(y) : "f"(x)); return y;
}
// ---- f32x2 packed math (sm_100+) ----
__device__ __forceinline__ ull pk2(float lo, float hi) {
    ull d; asm("mov.b64 %0, {%1, %2};" : "=l"(d) : "f"(lo), "f"(hi)); return d;
}
__device__ __forceinline__ void upk2(ull d, float& lo, float& hi) {
    asm("mov.b64 {%0, %1}, %2;" : "=f"(lo), "=f"(hi) : "l"(d));
}
__device__ __forceinline__ ull fma2(ull a, ull b, ull c) {
    ull d; asm("fma.rn.f32x2 %0, %1, %2, %3;" : "=l"(d) : "l"(a), "l"(b), "l"(c)); return d;
}
__device__ __forceinline__ ull mul2(ull a, ull b) {
    ull d; asm("mul.rn.f32x2 %0, %1, %2;" : "=l"(d) : "l"(a), "l"(b)); return d;
}
__device__ __forceinline__ ull add2(ull a, ull b) {
    ull d; asm("add.rn.f32x2 %0, %1, %2;" : "=l"(d) : "l"(a), "l"(b)); return d;
}

struct Tile { ulonglong2 kx, ky, kz, vx, vy, vz; };

struct SmemView {
    const ulonglong2 *kx, *ky, *kz, *vx, *vy, *vz;
};

__device__ __forceinline__ void load_tile(Tile& T, const SmemView& sv, int idx) {
    T.kx = sv.kx[idx]; T.ky = sv.ky[idx]; T.kz = sv.kz[idx];
    T.vx = sv.vx[idx]; T.vy = sv.vy[idx]; T.vz = sv.vz[idx];
}

__device__ __forceinline__ void body(const Tile& T,
    const ull (&qx2)[QPT], const ull (&qy2)[QPT], const ull (&qz2)[QPT],
    ull (&ssum2)[QPT], ull (&accx2)[QPT], ull (&accy2)[QPT], ull (&accz2)[QPT])
{
    #pragma unroll
    for (int p = 0; p < 2; p++) {
        ull kxx = p ? T.kx.y : T.kx.x;
        ull kyy = p ? T.ky.y : T.ky.x;
        ull kzz = p ? T.kz.y : T.kz.x;
        ull vxx = p ? T.vx.y : T.vx.x;
        ull vyy = p ? T.vy.y : T.vy.x;
        ull vzz = p ? T.vz.y : T.vz.x;
        #pragma unroll
        for (int i = 0; i < QPT; i++) {
            ull sc2 = fma2(qz2[i], kzz, fma2(qy2[i], kyy, mul2(qx2[i], kxx)));
            float s0, s1; upk2(sc2, s0, s1);
            ull w2 = pk2(ex2f(s0), ex2f(s1));
            ssum2[i] = add2(ssum2[i], w2);
            accx2[i] = fma2(w2, vxx, accx2[i]);
            accy2[i] = fma2(w2, vyy, accy2[i]);
            accz2[i] = fma2(w2, vzz, accz2[i]);
        }
    }
}

// Grid: (half=2, combo=3, batch=48). Block: 256 threads, 2 queries each
// (16 warps/SM at 2 blocks/SM -> 4 warps/SMSP for latency hiding).
// K/V stored component-major in smem so LDS.128 yields 4 consecutive keys'
// worth of one component = two pre-packed f32x2 key-pairs (no pack MOVs).
__global__ __launch_bounds__(NTHREADS) void attn_kernel(
    const float* __restrict__ x,
    const float* __restrict__ WQ, const float* __restrict__ bQ,
    const float* __restrict__ WK, const float* __restrict__ bK,
    const float* __restrict__ WV, const float* __restrict__ bV)
{
    __shared__ __align__(16) float sKx[SLEN], sKy[SLEN], sKz[SLEN];
    __shared__ __align__(16) float sVx[SLEN], sVy[SLEN], sVz[SLEN];
    __shared__ float red[6][NTHREADS];

    const int half = blockIdx.x;
    const int c    = blockIdx.y;
    const int b    = blockIdx.z;
    // a1=attn(Q2,K0,V1) ch0-2 ; a2=attn(Q0,K1,V2) ch3-5 ; a3=attn(Q1,K2,V0) ch6-8
    const int qb = (c + 2) % 3;
    const int kb = c;
    const int vb = (c + 1) % 3;
    const int tid = threadIdx.x;

    // band/batch base pointers into x: layout (3, B, S, 3)
    const float* xk = x + ((size_t)kb * BATCH + b) * SLEN * 3;
    const float* xv = x + ((size_t)vb * BATCH + b) * SLEN * 3;
    const float* xq = x + ((size_t)qb * BATCH + b) * SLEN * 3;

    // projection weights (tiny, L1/L2 resident)
    float wk[9], bkv[3], wv[9], bvv[3];
    #pragma unroll
    for (int i = 0; i < 9; i++) { wk[i] = WK[kb * 9 + i]; wv[i] = WV[vb * 9 + i]; }
    #pragma unroll
    for (int i = 0; i < 3; i++) { bkv[i] = bK[kb * 3 + i]; bvv[i] = bV[vb * 3 + i]; }

    // Fill K, V tiles (component-major)
    for (int s = tid; s < SLEN; s += NTHREADS) {
        float x0 = xk[s * 3 + 0], x1 = xk[s * 3 + 1], x2 = xk[s * 3 + 2];
        sKx[s] = fmaf(wk[2], x2, fmaf(wk[1], x1, fmaf(wk[0], x0, bkv[0])));
        sKy[s] = fmaf(wk[5], x2, fmaf(wk[4], x1, fmaf(wk[3], x0, bkv[1])));
        sKz[s] = fmaf(wk[8], x2, fmaf(wk[7], x1, fmaf(wk[6], x0, bkv[2])));
        float y0 = xv[s * 3 + 0], y1 = xv[s * 3 + 1], y2 = xv[s * 3 + 2];
        sVx[s] = fmaf(wv[2], y2, fmaf(wv[1], y1, fmaf(wv[0], y0, bvv[0])));
        sVy[s] = fmaf(wv[5], y2, fmaf(wv[4], y1, fmaf(wv[3], y0, bvv[1])));
        sVz[s] = fmaf(wv[8], y2, fmaf(wv[7], y1, fmaf(wv[6], y0, bvv[2])));
    }
    __syncthreads();

    // Per-thread queries, pre-scaled by log2(e)/sqrt(3) so ex2(q.k) == exp(score),
    // duplicated into both f32x2 lanes (key-pair broadcast).
    const float QS = (float)(1.4426950408889634 / 1.7320508075688772);
    float wq[9], bqv[3];
    #pragma unroll
    for (int i = 0; i < 9; i++) wq[i] = WQ[qb * 9 + i];
    #pragma unroll
    for (int i = 0; i < 3; i++) bqv[i] = bQ[qb * 3 + i];

    const int q0 = half * QBLK;
    ull qx2[QPT], qy2[QPT], qz2[QPT];
    ull ssum2[QPT], accx2[QPT], accy2[QPT], accz2[QPT];
    #pragma unroll
    for (int i = 0; i < QPT; i++) {
        int s = q0 + tid + i * NTHREADS;
        float x0 = xq[s * 3 + 0], x1 = xq[s * 3 + 1], x2 = xq[s * 3 + 2];
        float a0 = QS * fmaf(wq[2], x2, fmaf(wq[1], x1, fmaf(wq[0], x0, bqv[0])));
        float a1 = QS * fmaf(wq[5], x2, fmaf(wq[4], x1, fmaf(wq[3], x0, bqv[1])));
        float a2 = QS * fmaf(wq[8], x2, fmaf(wq[7], x1, fmaf(wq[6], x0, bqv[2])));
        qx2[i] = pk2(a0, a0); qy2[i] = pk2(a1, a1); qz2[i] = pk2(a2, a2);
        ssum2[i] = 0ull; accx2[i] = 0ull; accy2[i] = 0ull; accz2[i] = 0ull;
    }

    SmemView sv = { (const ulonglong2*)sKx, (const ulonglong2*)sKy,
                    (const ulonglong2*)sKz, (const ulonglong2*)sVx,
                    (const ulonglong2*)sVy, (const ulonglong2*)sVz };

    // Ping-pong software pipeline: tile t+1 fetched (LDS.128 broadcast,
    // ~29 cyc latency) before the MUFU body of tile t.
    // No tile-copy MOVs, no per-iter branch; final prefetch index clamped.
    Tile A, B;
    load_tile(A, sv, 0);
    for (int t4 = 0; t4 < NT4; t4 += 2) {
        load_tile(B, sv, t4 + 1);
        body(A, qx2, qy2, qz2, ssum2, accx2, accy2, accz2);
        load_tile(A, sv, min(t4 + 2, NT4 - 1));
        body(B, qx2, qy2, qz2, ssum2, accx2, accy2, accz2);
    }

    // Finalize (horizontal add of the two key-parity lanes), write out
    // (SoA, coalesced), accumulate per-channel partial stats.
    float ps[3] = {0.f, 0.f, 0.f}, pq[3] = {0.f, 0.f, 0.f};
    #pragma unroll
    for (int i = 0; i < QPT; i++) {
        float slo, shi, xlo, xhi, ylo, yhi, zlo, zhi;
        upk2(ssum2[i], slo, shi);
        upk2(accx2[i], xlo, xhi);
        upk2(accy2[i], ylo, yhi);
        upk2(accz2[i], zlo, zhi);
        float inv = rcpf(slo + shi);
        float o0 = (xlo + xhi) * inv, o1 = (ylo + yhi) * inv, o2 = (zlo + zhi) * inv;
        int row = b * SLEN + q0 + tid + i * NTHREADS;
        g_out[3 * c + 0][row] = o0;
        g_out[3 * c + 1][row] = o1;
        g_out[3 * c + 2][row] = o2;
        ps[0] += o0; ps[1] += o1; ps[2] += o2;
        pq[0] += o0 * o0; pq[1] += o1 * o1; pq[2] += o2 * o2;
    }

    // Deterministic block reduction of partial stats
    red[0][tid] = ps[0]; red[1][tid] = ps[1]; red[2][tid] = ps[2];
    red[3][tid] = pq[0]; red[4][tid] = pq[1]; red[5][tid] = pq[2];
    __syncthreads();
    for (int st = NTHREADS / 2; st > 0; st >>= 1) {
        if (tid < st) {
            #pragma unroll
            for (int j = 0; j < 6; j++) red[j][tid] += red[j][tid + st];
        }
        __syncthreads();
    }
    if (tid == 0) {
        int col = b * 2 + half;
        #pragma unroll
        for (int e = 0; e < 3; e++) {
            g_ps[(3 * c + e) * NPART + col] = red[e][0];
            g_pq[(3 * c + e) * NPART + col] = red[3 + e][0];
        }
    }
}

// Single-block: reduce stats partials once, fold BN into FC, publish w2/b2.
__global__ __launch_bounds__(NPART) void fold_kernel(
    const float* __restrict__ gamma, const float* __restrict__ beta,
    const float* __restrict__ fcw, const float* __restrict__ fcb)
{
    __shared__ float sps[9][NPART], spq[9][NPART];
    __shared__ float scale[9], shift[9];
    const int tid = threadIdx.x;

    // Stage partials: 96 threads x 9 channels, coalesced per channel.
    #pragma unroll
    for (int ch = 0; ch < 9; ch++) {
        sps[ch][tid] = g_ps[ch * NPART + tid];
        spq[ch][tid] = g_pq[ch * NPART + tid];
    }
    __syncthreads();
    // Tree-reduce 96 -> 3 per channel (fixed order, deterministic).
    for (int st = NPART / 2; st >= 3; st >>= 1) {
        for (int idx = tid; idx < 9 * st; idx += NPART) {
            int ch = idx / st, j = idx % st;
            sps[ch][j] += sps[ch][j + st];
            spq[ch][j] += spq[ch][j + st];
        }
        __syncthreads();
    }
    if (tid < 9) {
        float s  = sps[tid][0] + sps[tid][1] + sps[tid][2];
        float qq = spq[tid][0] + spq[tid][1] + spq[tid][2];
        float invn = 1.0f / (float)NROWS;
        float mean = s * invn;
        float var  = qq * invn - mean * mean;
        float sc = gamma[tid] * rsqrtf(var + 1e-5f);
        scale[tid] = sc;
        shift[tid] = beta[tid] - mean * sc;
    }
    __syncthreads();
    if (tid < 27) g_fw[tid] = fcw[tid] * scale[tid % 9];
    if (tid < 3) {
        float a = fcb[tid];
        #pragma unroll
        for (int cc = 0; cc < 9; cc++) a = fmaf(fcw[tid * 9 + cc], shift[cc], a);
        g_fb[tid] = a;
    }
}

// GEMV epilogue: y = g_out @ w2^T + b2 (BN already folded by fold_kernel).
__global__ __launch_bounds__(256) void bnfc_kernel(float* __restrict__ out)
{
    __shared__ float w2[27], b2s[3];
    const int tid = threadIdx.x;

    if (tid < 27) w2[tid] = g_fw[tid];
    if (tid < 3)  b2s[tid] = g_fb[tid];
    __syncthreads();

    int row = blockIdx.x * blockDim.x + tid;
    float v[9];
    #pragma unroll
    for (int cc = 0; cc < 9; cc++) v[cc] = g_out[cc][row];   // coalesced (SoA)
    #pragma unroll
    for (int j = 0; j < 3; j++) {
        float y = b2s[j];
        #pragma unroll
        for (int cc = 0; cc < 9; cc++) y = fmaf(w2[j * 9 + cc], v[cc], y);
        out[row * 3 + j] = y;
    }
}

extern "C" void kernel_launch(void* const* d_in, const int* in_sizes, int n_in,
                              void* d_out, int out_size)
{
    const float* x     = (const float*)d_in[0];
    const float* WQ    = (const float*)d_in[1];
    const float* bQ    = (const float*)d_in[2];
    const float* WK    = (const float*)d_in[3];
    const float* bK    = (const float*)d_in[4];
    const float* WV    = (const float*)d_in[5];
    const float* bV    = (const float*)d_in[6];
    const float* gamma = (const float*)d_in[7];
    const float* beta  = (const float*)d_in[8];
    const float* fcw   = (const float*)d_in[9];
    const float* fcb   = (const float*)d_in[10];

    dim3 g1(2, 3, BATCH);
    attn_kernel<<<g1, NTHREADS>>>(x, WQ, bQ, WK, bK, WV, bV);
    fold_kernel<<<1, NPART>>>(gamma, beta, fcw, fcb);
    bnfc_kernel<<<NROWS / 256, 256>>>((float*)d_out);
}